// round 15
// baseline (speedup 1.0000x reference)
#include <cuda_runtime.h>
#include <math.h>
#include <stdint.h>

// ---------------- problem constants (fixed shapes) ----------------
#define L_    4
#define B_    8
#define SQ    512
#define D_    1024
#define H_    16
#define DHD   64
#define T_    (B_*SQ)       // 4096
#define FFN_  4096
#define PAGE_ 16
#define PPS   80            // pages per seq
#define CACHED 48
#define KV    1280          // kv length per seq
#define NUM_PAGES 640

// ---------------- device scratch ----------------
__device__ float g_x[T_*D_];
__device__ float g_q[T_*D_];
__device__ float g_k[T_*D_];
__device__ float g_v[T_*D_];
__device__ float g_attn[T_*D_];
__device__ float g_tmp[T_*D_];
__device__ float g_h[T_*FFN_];
__device__ float g_Kf[(size_t)B_*H_*KV*DHD];   // [b*H+h][kv][dh]
__device__ float g_Vt[(size_t)B_*H_*DHD*KV];   // [b*H+h][dh][kv]
__device__ float g_Wt[(size_t)D_*FFN_];        // transposed weight scratch (reused)
__device__ float g_S[(size_t)B_*H_*SQ*KV];     // scores/probs

__device__ __forceinline__ float tf32f(float x) {
    float r; asm("cvt.rna.tf32.f32 %0, %1;" : "=f"(r) : "f"(x)); return r;
}

// m16n8k8 tf32 mma (PTX ISA, sm_80+; valid on plain sm_103 target)
__device__ __forceinline__ void mma8(float* d, const uint32_t* a, const uint32_t* b) {
    asm volatile("mma.sync.aligned.m16n8k8.row.col.f32.tf32.tf32.f32 "
                 "{%0,%1,%2,%3}, {%4,%5,%6,%7}, {%8,%9}, {%0,%1,%2,%3};"
                 : "+f"(d[0]), "+f"(d[1]), "+f"(d[2]), "+f"(d[3])
                 : "r"(a[0]), "r"(a[1]), "r"(a[2]), "r"(a[3]),
                   "r"(b[0]), "r"(b[1]));
}

// ---------------- 3xTF32 mma.sync GEMM ----------------
// C[m][n] = alpha * sum_k A[m][k]*B[n][k] (+bias[n]) (+GELU)
// A row-major [M][K] lda; B row-major [N][K] ldb. Tile 128x128, BK=32.
// 256 threads = 8 warps (2x4), warp tile 64x32. Batched via blockIdx.z.
#define PITCH   132                  // floats per smem k-row (128 + 4 pad)
#define CH_FLT  (32*PITCH)           // floats per operand array per stage
#define STG_FLT (4*CH_FLT)           // Ahi, Alo, Bhi, Blo
#define GEMM_SMEM (2*STG_FLT*4 + 1024)

template<bool GELU>
__global__ void __launch_bounds__(256)
gemm_mma(const float* __restrict__ A, const float* __restrict__ Bm,
         const float* __restrict__ bias, float* __restrict__ C,
         int M, int N, int K, int lda, int ldb, int ldc,
         int Hn, long aS, long aH, long bS, long bH, long cS, long cH,
         float alpha)
{
    extern __shared__ char dynsmem[];
    float* sm = (float*)(((uintptr_t)dynsmem + 1023) & ~(uintptr_t)1023);

    const int z  = blockIdx.z;
    const int zb = z / Hn;
    const int zh = z - zb * Hn;
    A  += zb*aS + zh*aH;
    Bm += zb*bS + zh*bH;
    C  += zb*cS + zh*cH;

    const int bm   = blockIdx.y * 128;
    const int bn   = blockIdx.x * 128;
    const int tid  = threadIdx.x;
    const int wid  = tid >> 5;
    const int lane = tid & 31;
    const int g    = lane >> 2;      // 0..7
    const int tig  = lane & 3;       // 0..3
    const int wm   = wid >> 2;       // 0..1  (64-row slab)
    const int wn   = wid & 3;        // 0..3  (32-col slab)

    float acc[4][4][4];
    #pragma unroll
    for (int i = 0; i < 4; i++)
        #pragma unroll
        for (int j = 0; j < 4; j++)
            #pragma unroll
            for (int q = 0; q < 4; q++) acc[i][j][q] = 0.f;

    const float* Ab = A + (long)bm * lda;

    const int nc = K >> 5;

    // ---- prologue: chunk 0 -> stage 0 ----
    {
        float* st = sm;
        #pragma unroll
        for (int i = 0; i < 4; i++) {
            const int f = tid + i*256;
            const int row = f >> 3, c4 = f & 7;
            const float4 v = *reinterpret_cast<const float4*>(
                Ab + (long)row * lda + c4*4);
            const float* vv = reinterpret_cast<const float*>(&v);
            #pragma unroll
            for (int j = 0; j < 4; j++) {
                const float h = tf32f(vv[j]);
                st[(c4*4 + j)*PITCH + row]          = h;
                st[CH_FLT + (c4*4 + j)*PITCH + row] = tf32f(vv[j] - h);
            }
        }
        #pragma unroll
        for (int i = 0; i < 4; i++) {
            const int f = tid + i*256;
            const int row = f >> 3, c4 = f & 7;
            float4 v = make_float4(0.f, 0.f, 0.f, 0.f);
            if (bn + row < N)
                v = *reinterpret_cast<const float4*>(
                    Bm + (long)(bn + row) * ldb + c4*4);
            const float* vv = reinterpret_cast<const float*>(&v);
            #pragma unroll
            for (int j = 0; j < 4; j++) {
                const float h = tf32f(vv[j]);
                st[2*CH_FLT + (c4*4 + j)*PITCH + row] = h;
                st[3*CH_FLT + (c4*4 + j)*PITCH + row] = tf32f(vv[j] - h);
            }
        }
    }
    __syncthreads();

    for (int c = 0; c < nc; c++) {
        const int s = c & 1;
        const bool more = (c + 1) < nc;

        // ---- prefetch next chunk into registers ----
        float4 av[4], bv[4];
        if (more) {
            const long ko = (long)(c + 1) * 32;
            #pragma unroll
            for (int i = 0; i < 4; i++) {
                const int f = tid + i*256;
                const int row = f >> 3, c4 = f & 7;
                av[i] = *reinterpret_cast<const float4*>(
                    Ab + (long)row * lda + ko + c4*4);
                bv[i] = make_float4(0.f, 0.f, 0.f, 0.f);
                if (bn + row < N)
                    bv[i] = *reinterpret_cast<const float4*>(
                        Bm + (long)(bn + row) * ldb + ko + c4*4);
            }
        }

        // ---- compute on stage s ----
        {
            const uint32_t* Ah = reinterpret_cast<const uint32_t*>(sm + s*STG_FLT);
            const uint32_t* Al = Ah + CH_FLT;
            const uint32_t* Bh = Ah + 2*CH_FLT;
            const uint32_t* Bl = Ah + 3*CH_FLT;
            #pragma unroll
            for (int ks = 0; ks < 4; ks++) {
                const int r0 = (ks*8 + tig)*PITCH;
                const int r1 = (ks*8 + tig + 4)*PITCH;
                uint32_t ah[4][4], al[4][4], bh[4][2], bl[4][2];
                #pragma unroll
                for (int am = 0; am < 4; am++) {
                    const int mb = wm*64 + am*16 + g;
                    ah[am][0] = Ah[r0 + mb];     ah[am][1] = Ah[r0 + mb + 8];
                    ah[am][2] = Ah[r1 + mb];     ah[am][3] = Ah[r1 + mb + 8];
                    al[am][0] = Al[r0 + mb];     al[am][1] = Al[r0 + mb + 8];
                    al[am][2] = Al[r1 + mb];     al[am][3] = Al[r1 + mb + 8];
                }
                #pragma unroll
                for (int an = 0; an < 4; an++) {
                    const int nb = wn*32 + an*8 + g;
                    bh[an][0] = Bh[r0 + nb];     bh[an][1] = Bh[r1 + nb];
                    bl[an][0] = Bl[r0 + nb];     bl[an][1] = Bl[r1 + nb];
                }
                #pragma unroll
                for (int am = 0; am < 4; am++)
                    #pragma unroll
                    for (int an = 0; an < 4; an++) {
                        mma8(acc[am][an], ah[am], bh[an]);
                        mma8(acc[am][an], ah[am], bl[an]);
                        mma8(acc[am][an], al[am], bh[an]);
                    }
            }
        }

        // ---- store prefetched chunk into stage s^1 ----
        if (more) {
            float* st = sm + (s ^ 1)*STG_FLT;
            #pragma unroll
            for (int i = 0; i < 4; i++) {
                const int f = tid + i*256;
                const int row = f >> 3, c4 = f & 7;
                const float* vv = reinterpret_cast<const float*>(&av[i]);
                #pragma unroll
                for (int j = 0; j < 4; j++) {
                    const float h = tf32f(vv[j]);
                    st[(c4*4 + j)*PITCH + row]          = h;
                    st[CH_FLT + (c4*4 + j)*PITCH + row] = tf32f(vv[j] - h);
                }
                const float* wv = reinterpret_cast<const float*>(&bv[i]);
                #pragma unroll
                for (int j = 0; j < 4; j++) {
                    const float h = tf32f(wv[j]);
                    st[2*CH_FLT + (c4*4 + j)*PITCH + row] = h;
                    st[3*CH_FLT + (c4*4 + j)*PITCH + row] = tf32f(wv[j] - h);
                }
            }
        }
        __syncthreads();
    }

    // ---- epilogue ----
    #pragma unroll
    for (int am = 0; am < 4; am++) {
        const int m0 = bm + wm*64 + am*16 + g;
        #pragma unroll
        for (int an = 0; an < 4; an++) {
            const int n0 = bn + wn*32 + an*8 + 2*tig;
            if (n0 < N) {
                float vals[4];
                #pragma unroll
                for (int q = 0; q < 4; q++) {
                    float val = acc[am][an][q] * alpha;
                    if (bias) val += bias[n0 + (q & 1)];
                    if (GELU) val = 0.5f * val *
                        (1.f + erff(val * 0.70710678118654752f));
                    vals[q] = val;
                }
                *reinterpret_cast<float2*>(&C[(long)m0 * ldc + n0]) =
                    make_float2(vals[0], vals[1]);
                *reinterpret_cast<float2*>(&C[(long)(m0 + 8) * ldc + n0]) =
                    make_float2(vals[2], vals[3]);
            }
        }
    }
}

// ---------------- weight transpose: out[n][k] = in[k][n] ----------------
__global__ void transpose_k(const float* __restrict__ in, float* __restrict__ out,
                            int Kd, int Nd)
{
    __shared__ float s[32][33];
    const int n0 = blockIdx.x * 32, k0 = blockIdx.y * 32;
    const int tx = threadIdx.x, ty = threadIdx.y;   // 32 x 8
    #pragma unroll
    for (int i = 0; i < 32; i += 8)
        s[ty + i][tx] = in[(long)(k0 + ty + i) * Nd + n0 + tx];
    __syncthreads();
    #pragma unroll
    for (int i = 0; i < 32; i += 8)
        out[(long)(n0 + ty + i) * Kd + k0 + tx] = s[tx][ty + i];
}

// ---------------- gather K into [b*H+h][kv][dh] ----------------
__global__ void gather_k_k(const float* __restrict__ PT, const int* __restrict__ idx,
                           const float* __restrict__ kk)
{
    const long e = (long)blockIdx.x * 256 + threadIdx.x;  // B*H*KV*64
    const int dh = (int)(e & 63);
    const long r = e >> 6;
    const int kv = (int)(r % KV);
    const int zz = (int)(r / KV);
    const int h  = zz % H_;
    const int b  = zz / H_;
    const int slot = kv >> 4, off = kv & 15;
    float val;
    if (slot < CACHED) {
        const int pid = idx[b*PPS + slot];
        val = PT[(long)pid*(2*PAGE_*H_*DHD) + (long)off*(H_*DHD) + h*DHD + dh];
    } else {
        const int t = b*SQ + (slot - CACHED)*PAGE_ + off;
        val = kk[(long)t*D_ + h*DHD + dh];
    }
    g_Kf[e] = val;
}

// ---------------- gather V transposed into [b*H+h][dh][kv] ----------------
__global__ void gather_vt_k(const float* __restrict__ PT, const int* __restrict__ idx,
                            const float* __restrict__ vv)
{
    __shared__ float s[32][65];
    const int zz  = blockIdx.y;
    const int h   = zz % H_;
    const int b   = zz / H_;
    const int kv0 = blockIdx.x * 32;
    const int tid = threadIdx.x;   // 256
    #pragma unroll
    for (int i = 0; i < 8; i++) {
        const int pos = tid + i*256;
        const int kvi = pos >> 6;
        const int dh  = pos & 63;
        const int kv  = kv0 + kvi;
        const int slot = kv >> 4, off = kv & 15;
        float val;
        if (slot < CACHED) {
            const int pid = idx[b*PPS + slot];
            val = PT[(long)pid*(2*PAGE_*H_*DHD) + (long)(PAGE_*H_*DHD)
                     + (long)off*(H_*DHD) + h*DHD + dh];
        } else {
            const int t = b*SQ + (slot - CACHED)*PAGE_ + off;
            val = vv[(long)t*D_ + h*DHD + dh];
        }
        s[kvi][dh] = val;
    }
    __syncthreads();
    #pragma unroll
    for (int i = 0; i < 8; i++) {
        const int pos = tid + i*256;
        const int dh  = pos >> 5;
        const int kvi = pos & 31;
        g_Vt[((long)zz*DHD + dh)*KV + kv0 + kvi] = s[kvi][dh];
    }
}

// ---------------- rowwise softmax over KV=1280 (in place) ----------------
__global__ void softmax_k(float* __restrict__ S)
{
    float* row = S + (long)blockIdx.x * KV;
    const int tid = threadIdx.x;   // 128
    float v[10];
    float mx = -1e30f;
    #pragma unroll
    for (int i = 0; i < 10; i++) { v[i] = row[tid + i*128]; mx = fmaxf(mx, v[i]); }
    __shared__ float redm[4], reds[4];
    #pragma unroll
    for (int o = 16; o; o >>= 1) mx = fmaxf(mx, __shfl_xor_sync(0xffffffffu, mx, o));
    if ((tid & 31) == 0) redm[tid >> 5] = mx;
    __syncthreads();
    mx = fmaxf(fmaxf(redm[0], redm[1]), fmaxf(redm[2], redm[3]));
    float ssum = 0.f;
    #pragma unroll
    for (int i = 0; i < 10; i++) { v[i] = expf(v[i] - mx); ssum += v[i]; }
    #pragma unroll
    for (int o = 16; o; o >>= 1) ssum += __shfl_xor_sync(0xffffffffu, ssum, o);
    if ((tid & 31) == 0) reds[tid >> 5] = ssum;
    __syncthreads();
    ssum = reds[0] + reds[1] + reds[2] + reds[3];
    const float inv = 1.f / ssum;
    #pragma unroll
    for (int i = 0; i < 10; i++) row[tid + i*128] = v[i] * inv;
}

// ---------------- fused residual-add + layernorm (in place on x) ----------------
__global__ void add_ln_k(float* __restrict__ x, const float* __restrict__ y,
                         const float* __restrict__ g, const float* __restrict__ b)
{
    const int row = blockIdx.x;
    const int tid = threadIdx.x;   // 256
    float v[4];
    float s = 0.f, s2 = 0.f;
    #pragma unroll
    for (int i = 0; i < 4; i++) {
        const int c = tid + i*256;
        const float t = x[(long)row*D_ + c] + y[(long)row*D_ + c];
        v[i] = t; s += t; s2 += t*t;
    }
    __shared__ float rs[8], rs2[8];
    #pragma unroll
    for (int o = 16; o; o >>= 1) {
        s  += __shfl_xor_sync(0xffffffffu, s,  o);
        s2 += __shfl_xor_sync(0xffffffffu, s2, o);
    }
    if ((tid & 31) == 0) { rs[tid >> 5] = s; rs2[tid >> 5] = s2; }
    __syncthreads();
    s = 0.f; s2 = 0.f;
    #pragma unroll
    for (int w = 0; w < 8; w++) { s += rs[w]; s2 += rs2[w]; }
    const float mean = s * (1.f / D_);
    const float var  = s2 * (1.f / D_) - mean * mean;
    const float rstd = rsqrtf(var + 1e-5f);
    #pragma unroll
    for (int i = 0; i < 4; i++) {
        const int c = tid + i*256;
        x[(long)row*D_ + c] = (v[i] - mean) * rstd * g[c] + b[c];
    }
}

__global__ void copy_k(float* __restrict__ dst, const float* __restrict__ src, int n)
{
    const int i = blockIdx.x * 256 + threadIdx.x;
    if (i < n) dst[i] = src[i];
}

// ---------------- launch ----------------
extern "C" void kernel_launch(void* const* d_in, const int* in_sizes, int n_in,
                              void* d_out, int out_size)
{
    const float* x         = (const float*)d_in[0];
    const int*   kvidx     = (const int*)  d_in[3];
    const float* pagetable = (const float*)d_in[5];
    const float* Wq  = (const float*)d_in[6];
    const float* bq  = (const float*)d_in[7];
    const float* Wk  = (const float*)d_in[8];
    const float* bk  = (const float*)d_in[9];
    const float* Wv  = (const float*)d_in[10];
    const float* bv  = (const float*)d_in[11];
    const float* Wo  = (const float*)d_in[12];
    const float* bo  = (const float*)d_in[13];
    const float* l1g = (const float*)d_in[14];
    const float* l1b = (const float*)d_in[15];
    const float* W1  = (const float*)d_in[16];
    const float* b1  = (const float*)d_in[17];
    const float* W2  = (const float*)d_in[18];
    const float* b2  = (const float*)d_in[19];
    const float* l2g = (const float*)d_in[20];
    const float* l2b = (const float*)d_in[21];
    float* out = (float*)d_out;

    float *px, *pq, *pk, *pv, *pattn, *ptmp, *ph, *pKf, *pVt, *pS, *pWt;
    cudaGetSymbolAddress((void**)&px,    g_x);
    cudaGetSymbolAddress((void**)&pq,    g_q);
    cudaGetSymbolAddress((void**)&pk,    g_k);
    cudaGetSymbolAddress((void**)&pv,    g_v);
    cudaGetSymbolAddress((void**)&pattn, g_attn);
    cudaGetSymbolAddress((void**)&ptmp,  g_tmp);
    cudaGetSymbolAddress((void**)&ph,    g_h);
    cudaGetSymbolAddress((void**)&pKf,   g_Kf);
    cudaGetSymbolAddress((void**)&pVt,   g_Vt);
    cudaGetSymbolAddress((void**)&pS,    g_S);
    cudaGetSymbolAddress((void**)&pWt,   g_Wt);

    cudaFuncSetAttribute(gemm_mma<false>,
        cudaFuncAttributeMaxDynamicSharedMemorySize, GEMM_SMEM);
    cudaFuncSetAttribute(gemm_mma<true>,
        cudaFuncAttributeMaxDynamicSharedMemorySize, GEMM_SMEM);

    copy_k<<<(T_*D_ + 255)/256, 256>>>(px, x, T_*D_);

    dim3 trD(32, 8);

    for (int l = 0; l < L_; l++) {
        const float* WqL = Wq + (long)l*D_*D_;
        const float* WkL = Wk + (long)l*D_*D_;
        const float* WvL = Wv + (long)l*D_*D_;
        const float* WoL = Wo + (long)l*D_*D_;
        const float* W1L = W1 + (long)l*D_*FFN_;
        const float* W2L = W2 + (long)l*FFN_*D_;
        const float* PTl = pagetable + (long)l * NUM_PAGES * 2 * PAGE_ * H_ * DHD;

        dim3 gDD(D_/128, T_/128, 1);      // 4096 x 1024

        // ---- QKV projections (transpose weight, then NT mma GEMM) ----
        transpose_k<<<dim3(D_/32, D_/32), trD>>>(WqL, pWt, D_, D_);
        gemm_mma<false><<<gDD, 256, GEMM_SMEM>>>(px, pWt, bq + (long)l*D_, pq,
            T_, D_, D_, D_, D_, D_, 1, 0, 0, 0, 0, 0, 0, 1.f);
        transpose_k<<<dim3(D_/32, D_/32), trD>>>(WkL, pWt, D_, D_);
        gemm_mma<false><<<gDD, 256, GEMM_SMEM>>>(px, pWt, bk + (long)l*D_, pk,
            T_, D_, D_, D_, D_, D_, 1, 0, 0, 0, 0, 0, 0, 1.f);
        transpose_k<<<dim3(D_/32, D_/32), trD>>>(WvL, pWt, D_, D_);
        gemm_mma<false><<<gDD, 256, GEMM_SMEM>>>(px, pWt, bv + (long)l*D_, pv,
            T_, D_, D_, D_, D_, D_, 1, 0, 0, 0, 0, 0, 0, 1.f);

        // ---- gather paged KV ----
        gather_k_k<<<(int)(((long)B_*H_*KV*DHD)/256), 256>>>(PTl, kvidx, pk);
        gather_vt_k<<<dim3(KV/32, B_*H_), 256>>>(PTl, kvidx, pv);

        // ---- scores: S[z] = 0.125 * Q_slice @ Kf[z]^T ----
        dim3 gS(KV/128, SQ/128, B_*H_);
        gemm_mma<false><<<gS, 256, GEMM_SMEM>>>(pq, pKf, nullptr, pS,
            SQ, KV, DHD, D_, DHD, KV,
            H_, (long)SQ*D_, 64L, (long)H_*KV*DHD, (long)KV*DHD,
            (long)H_*SQ*KV, (long)SQ*KV, 0.125f);

        softmax_k<<<B_*H_*SQ, 128>>>(pS);

        // ---- PV: O_slice = P[z] @ Vt[z]^T  (N = 64) ----
        dim3 gP(1, SQ/128, B_*H_);
        gemm_mma<false><<<gP, 256, GEMM_SMEM>>>(pS, pVt, nullptr, pattn,
            SQ, DHD, KV, KV, KV, D_,
            H_, (long)H_*SQ*KV, (long)SQ*KV, (long)H_*DHD*KV, (long)DHD*KV,
            (long)SQ*D_, 64L, 1.f);

        // ---- output projection + residual + LN1 ----
        transpose_k<<<dim3(D_/32, D_/32), trD>>>(WoL, pWt, D_, D_);
        gemm_mma<false><<<gDD, 256, GEMM_SMEM>>>(pattn, pWt, bo + (long)l*D_, ptmp,
            T_, D_, D_, D_, D_, D_, 1, 0, 0, 0, 0, 0, 0, 1.f);
        add_ln_k<<<T_, 256>>>(px, ptmp, l1g + (long)l*D_, l1b + (long)l*D_);

        // ---- FFN ----
        transpose_k<<<dim3(FFN_/32, D_/32), trD>>>(W1L, pWt, D_, FFN_);
        dim3 gF1(FFN_/128, T_/128, 1);
        gemm_mma<true><<<gF1, 256, GEMM_SMEM>>>(px, pWt, b1 + (long)l*FFN_, ph,
            T_, FFN_, D_, D_, D_, FFN_, 1, 0, 0, 0, 0, 0, 0, 1.f);
        transpose_k<<<dim3(D_/32, FFN_/32), trD>>>(W2L, pWt, FFN_, D_);
        dim3 gF2(D_/128, T_/128, 1);
        gemm_mma<false><<<gF2, 256, GEMM_SMEM>>>(ph, pWt, b2 + (long)l*D_, ptmp,
            T_, D_, FFN_, FFN_, FFN_, D_, 1, 0, 0, 0, 0, 0, 0, 1.f);
        add_ln_k<<<T_, 256>>>(px, ptmp, l2g + (long)l*D_, l2b + (long)l*D_);
    }

    copy_k<<<(T_*D_ + 255)/256, 256>>>(out, px, T_*D_);
}